// round 4
// baseline (speedup 1.0000x reference)
#include <cuda_runtime.h>
#include <cuda_fp16.h>
#include <cstdint>

#define H_  32
#define SQ_ 2048
#define SK_ 2048
#define DH_ 128
#define QT  128          // q rows per CTA
#define KT  64           // k per cp.async chunk
#define NCH (SK_/KT)     // 32 chunks
#define NKS (SK_/16)     // 128 ksteps

// V converted to fp16, natural [h][k][d] layout
__device__ alignas(16) __half g_vh[(size_t)H_ * SK_ * DH_];

__device__ __forceinline__ uint32_t smem_u32(const void* p) {
    uint32_t a;
    asm("{ .reg .u64 t; cvta.to.shared.u64 t, %1; cvt.u32.u64 %0, t; }" : "=r"(a) : "l"(p));
    return a;
}

#define MMA16816(D, A, B0, B1) \
    asm volatile( \
        "mma.sync.aligned.m16n8k16.row.col.f32.f16.f16.f32 " \
        "{%0,%1,%2,%3}, {%4,%5,%6,%7}, {%8,%9}, {%0,%1,%2,%3};" \
        : "+f"((D)[0]), "+f"((D)[1]), "+f"((D)[2]), "+f"((D)[3]) \
        : "r"((A)[0]), "r"((A)[1]), "r"((A)[2]), "r"((A)[3]), \
          "r"(B0), "r"(B1))

// ---------------- V fp32 -> fp16 convert ----------------
__global__ void convert_v_kernel(const float* __restrict__ v) {
    size_t i = ((size_t)blockIdx.x * 256 + threadIdx.x) * 8;
    float4 a = *(const float4*)(v + i);
    float4 b = *(const float4*)(v + i + 4);
    __half2 h0 = __floats2half2_rn(a.x, a.y);
    __half2 h1 = __floats2half2_rn(a.z, a.w);
    __half2 h2 = __floats2half2_rn(b.x, b.y);
    __half2 h3 = __floats2half2_rn(b.z, b.w);
    uint4 o;
    o.x = *(uint32_t*)&h0; o.y = *(uint32_t*)&h1;
    o.z = *(uint32_t*)&h2; o.w = *(uint32_t*)&h3;
    *(uint4*)(g_vh + i) = o;
}

// ---------------- Main fused kernel ----------------
// CTA: 256 threads = 8 warps. Warp w handles q rows [16w, 16w+16), all n=128.
// Accum: 16 ntiles x 4 = 64 fp32 regs per lane.
__global__ void __launch_bounds__(256, 2)
attn_sink_kernel(const float* __restrict__ logits,
                 const float* __restrict__ sinks,
                 float* __restrict__ out)
{
    __shared__ __align__(128) char vsm[2][16384];   // V stages: 64k x 128d fp16, swizzled
    __shared__ float rowsum[QT];

    const int tid = threadIdx.x;
    const int w   = tid >> 5;
    const int l   = tid & 31;
    const int h   = blockIdx.x >> 4;
    const int q0  = (blockIdx.x & 15) * QT;

    const float*  Lbase = logits + ((size_t)h * SQ_ + q0 + w * 16) * SK_;
    const __half* Vh    = g_vh + (size_t)h * SK_ * DH_;
    const uint32_t vb   = smem_u32(vsm);

    // L load pattern: inst i (0..1): lane l -> row 8i + (l>>2), cols 4*(l&3) + 16*gk .. +3
    const float* Lr[2];
#pragma unroll
    for (int i = 0; i < 2; i++)
        Lr[i] = Lbase + (size_t)(8 * i + (l >> 2)) * SK_ + 4 * (l & 3);

    // ldmatrix lane geometry (x4.trans)
    const int lu = l >> 4;                       // n +8 select
    const int kl = (l & 7) + 8 * ((l >> 3) & 1); // k row within kstep
    // shuffle source base for A frags
    const int s0  = (l & 28) | ((l & 3) >> 1);
    const bool odd = l & 1;

    float acc[16][4];
#pragma unroll
    for (int nt = 0; nt < 16; nt++)
#pragma unroll
        for (int c = 0; c < 4; c++) acc[nt][c] = 0.f;

    float psum[2] = {0.f, 0.f};

    // prologue: cp.async chunk 0 -> stage 0 (1024 x 16B lines, 256 threads x 4)
    {
#pragma unroll
        for (int u = 0; u < 4; u++) {
            int c = u * 256 + tid;
            int k = c >> 4, d = (c & 15) * 8;
            uint32_t dst = vb + (uint32_t)((d >> 6) << 13) + (uint32_t)(k << 7)
                         + (uint32_t)((((d >> 3) & 7) ^ (k & 7)) << 4);
            const __half* src = Vh + (size_t)k * DH_ + d;
            asm volatile("cp.async.cg.shared.global [%0], [%1], 16;" :: "r"(dst), "l"(src));
        }
        asm volatile("cp.async.commit_group;");
    }

    // prefetch first kstep of L
    float4 lv[2];
#pragma unroll
    for (int i = 0; i < 2; i++) lv[i] = *(const float4*)(Lr[i]);

    for (int ch = 0; ch < NCH; ch++) {
        __syncthreads();                         // stage (ch+1)&1 free to overwrite
        if (ch + 1 < NCH) {
            int s = (ch + 1) & 1;
#pragma unroll
            for (int u = 0; u < 4; u++) {
                int c = u * 256 + tid;
                int k = c >> 4, d = (c & 15) * 8;
                uint32_t dst = vb + (uint32_t)(s * 16384) + (uint32_t)((d >> 6) << 13)
                             + (uint32_t)(k << 7)
                             + (uint32_t)((((d >> 3) & 7) ^ (k & 7)) << 4);
                const __half* src = Vh + (size_t)((ch + 1) * KT + k) * DH_ + d;
                asm volatile("cp.async.cg.shared.global [%0], [%1], 16;" :: "r"(dst), "l"(src));
            }
        }
        asm volatile("cp.async.commit_group;");
        asm volatile("cp.async.wait_group 1;");  // chunk ch resident
        __syncthreads();

        const uint32_t vstage = vb + (uint32_t)((ch & 1) * 16384);

#pragma unroll
        for (int j = 0; j < 4; j++) {
            const int gk = ch * 4 + j;

            // prefetch next kstep L
            float4 nv[2];
            if (gk < NKS - 1) {
#pragma unroll
                for (int i = 0; i < 2; i++)
                    nv[i] = *(const float4*)(Lr[i] + (size_t)(gk + 1) * 16);
            } else {
#pragma unroll
                for (int i = 0; i < 2; i++) nv[i] = lv[i];
            }

            // exp + rowsum + pack fp16
            uint32_t h2v[2][2];
#pragma unroll
            for (int i = 0; i < 2; i++) {
                float e0 = __expf(lv[i].x), e1 = __expf(lv[i].y);
                float e2 = __expf(lv[i].z), e3 = __expf(lv[i].w);
                psum[i] += (e0 + e1) + (e2 + e3);
                __half2 p0 = __floats2half2_rn(e0, e1);
                __half2 p1 = __floats2half2_rn(e2, e3);
                h2v[i][0] = *(uint32_t*)&p0;
                h2v[i][1] = *(uint32_t*)&p1;
            }

            // form A fragments via shuffles:
            // frag reg (a, b): row = 8a+g (g=l>>2), k = 16j+8b+2d (d=l&3)
            uint32_t af[4];
#pragma unroll
            for (int a = 0; a < 2; a++)
#pragma unroll
                for (int b = 0; b < 2; b++) {
                    uint32_t lo = __shfl_sync(0xffffffffu, h2v[a][0], s0 + 2 * b);
                    uint32_t hi = __shfl_sync(0xffffffffu, h2v[a][1], s0 + 2 * b);
                    af[a + 2 * b] = odd ? hi : lo;
                }

            const uint32_t rowoff = (uint32_t)((16 * j + kl) << 7);
#pragma unroll
            for (int nt = 0; nt < 16; nt += 2) {
                int u = nt + lu;
                uint32_t addr = vstage + (uint32_t)((u >> 3) << 13) + rowoff
                              + (uint32_t)(((u & 7) ^ (l & 7)) << 4);
                uint32_t b0, b1, b2, b3;
                asm volatile(
                    "ldmatrix.sync.aligned.m8n8.x4.trans.shared.b16 {%0,%1,%2,%3}, [%4];"
                    : "=r"(b0), "=r"(b1), "=r"(b2), "=r"(b3) : "r"(addr));
                MMA16816(acc[nt],     af, b0, b1);
                MMA16816(acc[nt + 1], af, b2, b3);
            }

#pragma unroll
            for (int i = 0; i < 2; i++) lv[i] = nv[i];
        }
    }

    // rowsum reduce: psum[i] covers row 8i + (l>>2); 4 lanes (xor 1,2) share a row
#pragma unroll
    for (int i = 0; i < 2; i++) {
        float v = psum[i];
        v += __shfl_xor_sync(0xffffffffu, v, 1);
        v += __shfl_xor_sync(0xffffffffu, v, 2);
        if ((l & 3) == 0) rowsum[w * 16 + 8 * i + (l >> 2)] = v;
    }
    __syncthreads();

    // epilogue: O = acc / (rowsum + exp(sink))
    const float sinkv = __expf(sinks[h]);
#pragma unroll
    for (int a = 0; a < 2; a++) {
        int r = w * 16 + 8 * a + (l >> 2);
        float inv = 1.0f / (rowsum[r] + sinkv);
        float* orow = out + ((size_t)h * SQ_ + q0 + r) * DH_ + (l & 3) * 2;
#pragma unroll
        for (int nt = 0; nt < 16; nt++) {
            float2 o;
            o.x = acc[nt][2 * a + 0] * inv;
            o.y = acc[nt][2 * a + 1] * inv;
            *(float2*)(orow + nt * 8) = o;
        }
    }
}

// ---------------- Launch ----------------
extern "C" void kernel_launch(void* const* d_in, const int* in_sizes, int n_in,
                              void* d_out, int out_size) {
    const float* logits = nullptr;
    const float* value  = nullptr;
    const float* sinks  = nullptr;
    for (int i = 0; i < n_in; i++) {
        if (in_sizes[i] == H_) sinks = (const float*)d_in[i];
        else if (in_sizes[i] == H_ * SQ_ * SK_) logits = (const float*)d_in[i];
        else if (in_sizes[i] == H_ * SK_ * DH_) value = (const float*)d_in[i];
    }
    float* out = (float*)d_out;

    // V fp32 -> fp16 (8 elems/thread)
    convert_v_kernel<<<(H_ * SK_ * DH_) / (256 * 8), 256>>>(value);

    attn_sink_kernel<<<H_ * (SQ_ / QT), 256>>>(logits, sinks, out);
}

// round 5
// speedup vs baseline: 1.1413x; 1.1413x over previous
#include <cuda_runtime.h>
#include <cuda_fp16.h>
#include <cstdint>

#define H_  32
#define SQ_ 2048
#define SK_ 2048
#define DH_ 128
#define QT  128          // q rows per CTA
#define KT  64           // k per chunk
#define NCH (SK_/KT)     // 32 chunks

// SMEM layout (dynamic):
//   L stages: 2 x 128 rows x 272 B (68 floats, 64 data + 4 pad)  = 69632
//   V stages: 2 x 16384 (64k x 128d fp16, xor-swizzled)          = 32768
//   rowsum:   128 floats
#define LSTRIDE 272
#define LSTAGE  (QT * LSTRIDE)        // 34816
#define OFF_V   (2 * LSTAGE)          // 69632
#define OFF_SUM (OFF_V + 2 * 16384)   // 102400
#define SMEM_SZ (OFF_SUM + 512)       // 102912

// V converted to fp16, natural [h][k][d] layout
__device__ alignas(16) __half g_vh[(size_t)H_ * SK_ * DH_];

__device__ __forceinline__ uint32_t smem_u32(const void* p) {
    uint32_t a;
    asm("{ .reg .u64 t; cvta.to.shared.u64 t, %1; cvt.u32.u64 %0, t; }" : "=r"(a) : "l"(p));
    return a;
}

#define MMA16816(D, A, B0, B1) \
    asm volatile( \
        "mma.sync.aligned.m16n8k16.row.col.f32.f16.f16.f32 " \
        "{%0,%1,%2,%3}, {%4,%5,%6,%7}, {%8,%9}, {%0,%1,%2,%3};" \
        : "+f"((D)[0]), "+f"((D)[1]), "+f"((D)[2]), "+f"((D)[3]) \
        : "r"((A)[0]), "r"((A)[1]), "r"((A)[2]), "r"((A)[3]), \
          "r"(B0), "r"(B1))

// ---------------- V fp32 -> fp16 convert ----------------
__global__ void convert_v_kernel(const float* __restrict__ v) {
    size_t i = ((size_t)blockIdx.x * 256 + threadIdx.x) * 8;
    float4 a = *(const float4*)(v + i);
    float4 b = *(const float4*)(v + i + 4);
    __half2 h0 = __floats2half2_rn(a.x, a.y);
    __half2 h1 = __floats2half2_rn(a.z, a.w);
    __half2 h2 = __floats2half2_rn(b.x, b.y);
    __half2 h3 = __floats2half2_rn(b.z, b.w);
    uint4 o;
    o.x = *(uint32_t*)&h0; o.y = *(uint32_t*)&h1;
    o.z = *(uint32_t*)&h2; o.w = *(uint32_t*)&h3;
    *(uint4*)(g_vh + i) = o;
}

// ---------------- Main fused kernel ----------------
// 256 threads = 8 warps. Warp w: q rows [16w,16w+16), n = all 128.
__global__ void __launch_bounds__(256, 2)
attn_sink_kernel(const float* __restrict__ logits,
                 const float* __restrict__ sinks,
                 float* __restrict__ out)
{
    extern __shared__ char smem[];
    char* Lsm = smem;
    float* rowsum = (float*)(smem + OFF_SUM);

    const int tid = threadIdx.x;
    const int w   = tid >> 5;
    const int l   = tid & 31;
    const int h   = blockIdx.x >> 4;
    const int q0  = (blockIdx.x & 15) * QT;

    const float*  Lsrc = logits + ((size_t)h * SQ_ + q0) * SK_;   // CTA base
    const __half* Vh   = g_vh + (size_t)h * SK_ * DH_;
    const uint32_t vb  = smem_u32(smem + OFF_V);
    const uint32_t lbu = smem_u32(smem);

    // mma lane geometry
    const int g  = l >> 2;        // row group
    const int m  = l & 3;         // k pair
    const int lu = l >> 4;                        // ldmatrix n +8 select
    const int kl = (l & 7) + 8 * ((l >> 3) & 1);  // ldmatrix k row

    float acc[16][4];
#pragma unroll
    for (int nt = 0; nt < 16; nt++)
#pragma unroll
        for (int c = 0; c < 4; c++) acc[nt][c] = 0.f;
    float psum[2] = {0.f, 0.f};

    // ---- async loaders ----
    // L chunk: 128 rows x 16 granules(16B); 2048 granules / 256 thr = 8 each
    auto load_L = [&](int ch, int s) {
#pragma unroll
        for (int u = 0; u < 8; u++) {
            int gi = u * 256 + tid;
            int row = gi >> 4, gc = gi & 15;
            uint32_t dst = lbu + (uint32_t)(s * LSTAGE + row * LSTRIDE + gc * 16);
            const float* src = Lsrc + (size_t)row * SK_ + ch * KT + gc * 4;
            asm volatile("cp.async.cg.shared.global [%0], [%1], 16;" :: "r"(dst), "l"(src));
        }
    };
    // V chunk: 64k x 128d fp16 = 1024 granules / 256 thr = 4 each
    auto load_V = [&](int ch, int s) {
#pragma unroll
        for (int u = 0; u < 4; u++) {
            int c = u * 256 + tid;
            int k = c >> 4, d = (c & 15) * 8;
            uint32_t dst = vb + (uint32_t)(s * 16384) + (uint32_t)((d >> 6) << 13)
                         + (uint32_t)(k << 7)
                         + (uint32_t)((((d >> 3) & 7) ^ (k & 7)) << 4);
            const __half* src = Vh + (size_t)(ch * KT + k) * DH_ + d;
            asm volatile("cp.async.cg.shared.global [%0], [%1], 16;" :: "r"(dst), "l"(src));
        }
    };

    // prologue: chunk 0 -> stage 0
    load_L(0, 0);
    load_V(0, 0);
    asm volatile("cp.async.commit_group;");

    for (int ch = 0; ch < NCH; ch++) {
        __syncthreads();                 // all warps done reading stage s^1
        if (ch + 1 < NCH) {
            int s = (ch + 1) & 1;
            load_L(ch + 1, s);
            load_V(ch + 1, s);
        }
        asm volatile("cp.async.commit_group;");
        asm volatile("cp.async.wait_group 1;");   // chunk ch resident
        __syncthreads();

        const uint32_t vstage = vb + (uint32_t)((ch & 1) * 16384);
        const char* Lst = Lsm + (ch & 1) * LSTAGE + (w * 16 + g) * LSTRIDE + m * 8;

#pragma unroll
        for (int j = 0; j < 4; j++) {
            // A fragments: LDS + exp + pack
            uint32_t af[4];
#pragma unroll
            for (int a = 0; a < 2; a++)
#pragma unroll
                for (int b = 0; b < 2; b++) {
                    float2 xv = *(const float2*)(Lst + a * (8 * LSTRIDE) + (16 * j + 8 * b) * 4);
                    float e0 = __expf(xv.x), e1 = __expf(xv.y);
                    psum[a] += e0 + e1;
                    __half2 p = __floats2half2_rn(e0, e1);
                    af[a + 2 * b] = *(uint32_t*)&p;
                }

            const uint32_t rowoff = (uint32_t)((16 * j + kl) << 7);
#pragma unroll
            for (int nt = 0; nt < 16; nt += 2) {
                int u = nt + lu;
                uint32_t addr = vstage + (uint32_t)((u >> 3) << 13) + rowoff
                              + (uint32_t)(((u & 7) ^ (l & 7)) << 4);
                uint32_t b0, b1, b2, b3;
                asm volatile(
                    "ldmatrix.sync.aligned.m8n8.x4.trans.shared.b16 {%0,%1,%2,%3}, [%4];"
                    : "=r"(b0), "=r"(b1), "=r"(b2), "=r"(b3) : "r"(addr));
                MMA16816(acc[nt],     af, b0, b1);
                MMA16816(acc[nt + 1], af, b2, b3);
            }
        }
    }

    // rowsum reduce: psum[a] covers row w*16 + 8a + g; lanes xor 1,2 share row
#pragma unroll
    for (int a = 0; a < 2; a++) {
        float v = psum[a];
        v += __shfl_xor_sync(0xffffffffu, v, 1);
        v += __shfl_xor_sync(0xffffffffu, v, 2);
        if (m == 0) rowsum[w * 16 + 8 * a + g] = v;
    }
    __syncthreads();

    // epilogue: O = acc / (rowsum + exp(sink))
    const float sinkv = __expf(sinks[h]);
#pragma unroll
    for (int a = 0; a < 2; a++) {
        int r = w * 16 + 8 * a + g;
        float inv = 1.0f / (rowsum[r] + sinkv);
        float* orow = out + ((size_t)h * SQ_ + q0 + r) * DH_ + m * 2;
#pragma unroll
        for (int nt = 0; nt < 16; nt++) {
            float2 o;
            o.x = acc[nt][2 * a + 0] * inv;
            o.y = acc[nt][2 * a + 1] * inv;
            *(float2*)(orow + nt * 8) = o;
        }
    }
}

// ---------------- Launch ----------------
extern "C" void kernel_launch(void* const* d_in, const int* in_sizes, int n_in,
                              void* d_out, int out_size) {
    const float* logits = nullptr;
    const float* value  = nullptr;
    const float* sinks  = nullptr;
    for (int i = 0; i < n_in; i++) {
        if (in_sizes[i] == H_) sinks = (const float*)d_in[i];
        else if (in_sizes[i] == H_ * SQ_ * SK_) logits = (const float*)d_in[i];
        else if (in_sizes[i] == H_ * SK_ * DH_) value = (const float*)d_in[i];
    }
    float* out = (float*)d_out;

    convert_v_kernel<<<(H_ * SK_ * DH_) / (256 * 8), 256>>>(value);

    cudaFuncSetAttribute(attn_sink_kernel,
                         cudaFuncAttributeMaxDynamicSharedMemorySize, SMEM_SZ);
    attn_sink_kernel<<<H_ * (SQ_ / QT), 256, SMEM_SZ>>>(logits, sinks, out);
}

// round 6
// speedup vs baseline: 1.1726x; 1.0274x over previous
#include <cuda_runtime.h>
#include <cuda_fp16.h>
#include <cstdint>

#define H_  32
#define SQ_ 2048
#define SK_ 2048
#define DH_ 128
#define QT  128          // q rows per CTA
#define KT  32           // k per chunk
#define NCH (SK_/KT)     // 64 chunks
#define NST 3            // pipeline stages

// SMEM layout (dynamic):
#define LSTRIDE 144                       // 128 B data + 16 pad (conflict-free LDS.128)
#define LSTAGE  (128 * LSTRIDE)           // 18432
#define VSTAGE  8192                      // 32k x 128d fp16, xor-swizzled
#define OFF_V   (NST * LSTAGE)            // 55296
#define OFF_P   (OFF_V + NST * VSTAGE)    // 79872
#define OFF_SUM (OFF_P + 8192)            // 88064
#define SMEM_SZ (OFF_SUM + 512)           // 88576

// V converted to fp16, natural [h][k][d] layout
__device__ alignas(16) __half g_vh[(size_t)H_ * SK_ * DH_];

__device__ __forceinline__ uint32_t smem_u32(const void* p) {
    uint32_t a;
    asm("{ .reg .u64 t; cvta.to.shared.u64 t, %1; cvt.u32.u64 %0, t; }" : "=r"(a) : "l"(p));
    return a;
}

#define MMA16816(D, A, B0, B1) \
    asm volatile( \
        "mma.sync.aligned.m16n8k16.row.col.f32.f16.f16.f32 " \
        "{%0,%1,%2,%3}, {%4,%5,%6,%7}, {%8,%9}, {%0,%1,%2,%3};" \
        : "+f"((D)[0]), "+f"((D)[1]), "+f"((D)[2]), "+f"((D)[3]) \
        : "r"((A)[0]), "r"((A)[1]), "r"((A)[2]), "r"((A)[3]), \
          "r"(B0), "r"(B1))

// ---------------- V fp32 -> fp16 convert ----------------
__global__ void convert_v_kernel(const float* __restrict__ v) {
    size_t i = ((size_t)blockIdx.x * 256 + threadIdx.x) * 8;
    float4 a = *(const float4*)(v + i);
    float4 b = *(const float4*)(v + i + 4);
    __half2 h0 = __floats2half2_rn(a.x, a.y);
    __half2 h1 = __floats2half2_rn(a.z, a.w);
    __half2 h2 = __floats2half2_rn(b.x, b.y);
    __half2 h3 = __floats2half2_rn(b.z, b.w);
    uint4 o;
    o.x = *(uint32_t*)&h0; o.y = *(uint32_t*)&h1;
    o.z = *(uint32_t*)&h2; o.w = *(uint32_t*)&h3;
    *(uint4*)(g_vh + i) = o;
}

// ---------------- Main fused kernel ----------------
// 256 threads = 8 warps. Warp w: q rows [32*(w&3), +32), n cols [64*(w>>2), +64).
__global__ void __launch_bounds__(256, 2)
attn_sink_kernel(const float* __restrict__ logits,
                 const float* __restrict__ sinks,
                 float* __restrict__ out)
{
    extern __shared__ char smem[];
    float* rowsum = (float*)(smem + OFF_SUM);

    const int tid = threadIdx.x;
    const int w   = tid >> 5;
    const int l   = tid & 31;
    const int h   = blockIdx.x >> 4;
    const int q0  = (blockIdx.x & 15) * QT;

    const int qw = w & 3;      // q 32-group
    const int nh = w >> 2;     // n 64-half
    const int g  = l >> 2;     // acc row group
    const int m  = l & 3;      // acc col pair
    const int lu = l >> 4;
    const int kl = (l & 7) + 8 * ((l >> 3) & 1);

    // exp-phase mapping: thread -> (row, k-half)
    const int er = tid >> 1;
    const int eh = tid & 1;
    const int esp = ((er >> 1) ^ (er >> 3)) & 3;   // P store swizzle

    const float*  Lsrc = logits + ((size_t)h * SQ_ + q0) * SK_;
    const __half* Vh   = g_vh + (size_t)h * SK_ * DH_;
    const uint32_t lb  = smem_u32(smem);
    const uint32_t vb  = lb + OFF_V;
    const uint32_t pbu = lb + OFF_P;

    // A-ldmatrix precomputed per-mtile base/swizzle
    uint32_t pA[2], spA[2];
#pragma unroll
    for (int mt = 0; mt < 2; mt++) {
        int R = 32 * qw + 16 * mt + kl;
        pA[mt]  = pbu + (uint32_t)(R * 64);
        spA[mt] = (uint32_t)(((R >> 1) ^ (R >> 3)) & 3);
    }
    // B-ldmatrix precomputed per-ntile offsets
    uint32_t uB[4];
#pragma unroll
    for (int nt = 0; nt < 4; nt++) {
        int u = 8 * nh + 2 * nt + lu;
        uB[nt] = (uint32_t)(((u >> 3) << 12) + (((u & 7) ^ (l & 7)) << 4));
    }

    float acc[2][8][4];
#pragma unroll
    for (int mt = 0; mt < 2; mt++)
#pragma unroll
        for (int nt = 0; nt < 8; nt++)
#pragma unroll
            for (int c = 0; c < 4; c++) acc[mt][nt][c] = 0.f;
    float psum = 0.f;

    auto load_chunk = [&](int c) {
        const int s = c % NST;
        // L: 128 rows x 8 granules = 1024 / 256 thr = 4 each
#pragma unroll
        for (int u = 0; u < 4; u++) {
            int gi = u * 256 + tid;
            int row = gi >> 3, gc = gi & 7;
            uint32_t dst = lb + (uint32_t)(s * LSTAGE + row * LSTRIDE + gc * 16);
            const float* src = Lsrc + (size_t)row * SK_ + c * KT + gc * 4;
            asm volatile("cp.async.cg.shared.global [%0], [%1], 16;" :: "r"(dst), "l"(src));
        }
        // V: 32k x 16 granules = 512 / 256 thr = 2 each
#pragma unroll
        for (int u = 0; u < 2; u++) {
            int ci = u * 256 + tid;
            int k = ci >> 4, d = (ci & 15) * 8;
            uint32_t dst = vb + (uint32_t)(s * VSTAGE) + (uint32_t)((d >> 6) << 12)
                         + (uint32_t)(k << 7)
                         + (uint32_t)((((d >> 3) & 7) ^ (k & 7)) << 4);
            const __half* src = Vh + (size_t)(c * KT + k) * DH_ + d;
            asm volatile("cp.async.cg.shared.global [%0], [%1], 16;" :: "r"(dst), "l"(src));
        }
    };

    // prologue: chunks 0,1
    load_chunk(0);
    asm volatile("cp.async.commit_group;");
    load_chunk(1);
    asm volatile("cp.async.commit_group;");

    for (int c = 0; c < NCH; c++) {
        __syncthreads();                       // stage (c-1)%NST + P free
        if (c + 2 < NCH) load_chunk(c + 2);
        asm volatile("cp.async.commit_group;");
        asm volatile("cp.async.wait_group 2;");
        __syncthreads();                       // chunk c visible to all

        // ---- exp phase: L[c] -> P (fp16, swizzled), rowsum ----
        {
            const char* lrow = smem + (c % NST) * LSTAGE + er * LSTRIDE + eh * 64;
            float4 xa = *(const float4*)(lrow);
            float4 xb = *(const float4*)(lrow + 16);
            float4 xc = *(const float4*)(lrow + 32);
            float4 xd = *(const float4*)(lrow + 48);
            float e0 = __expf(xa.x), e1 = __expf(xa.y), e2 = __expf(xa.z), e3 = __expf(xa.w);
            float e4 = __expf(xb.x), e5 = __expf(xb.y), e6 = __expf(xb.z), e7 = __expf(xb.w);
            float e8 = __expf(xc.x), e9 = __expf(xc.y), ea = __expf(xc.z), eb = __expf(xc.w);
            float ec = __expf(xd.x), ed = __expf(xd.y), ee = __expf(xd.z), ef = __expf(xd.w);
            psum += ((e0 + e1) + (e2 + e3)) + ((e4 + e5) + (e6 + e7))
                  + ((e8 + e9) + (ea + eb)) + ((ec + ed) + (ee + ef));
            __half2 p0 = __floats2half2_rn(e0, e1), p1 = __floats2half2_rn(e2, e3);
            __half2 p2 = __floats2half2_rn(e4, e5), p3 = __floats2half2_rn(e6, e7);
            __half2 p4 = __floats2half2_rn(e8, e9), p5 = __floats2half2_rn(ea, eb);
            __half2 p6 = __floats2half2_rn(ec, ed), p7 = __floats2half2_rn(ee, ef);
            uint4 o0, o1;
            o0.x = *(uint32_t*)&p0; o0.y = *(uint32_t*)&p1;
            o0.z = *(uint32_t*)&p2; o0.w = *(uint32_t*)&p3;
            o1.x = *(uint32_t*)&p4; o1.y = *(uint32_t*)&p5;
            o1.z = *(uint32_t*)&p6; o1.w = *(uint32_t*)&p7;
            char* pr = smem + OFF_P + er * 64;
            *(uint4*)(pr + (((2 * eh + 0) ^ esp) << 4)) = o0;
            *(uint4*)(pr + (((2 * eh + 1) ^ esp) << 4)) = o1;
        }
        __syncthreads();                       // P[c] complete

        // ---- MMA phase: P x V[c] ----
        const uint32_t vst = vb + (uint32_t)((c % NST) * VSTAGE);
#pragma unroll
        for (int j = 0; j < 2; j++) {
            uint32_t a[2][4];
#pragma unroll
            for (int mt = 0; mt < 2; mt++) {
                uint32_t pa = pA[mt] + ((((uint32_t)(lu + 2 * j)) ^ spA[mt]) << 4);
                asm volatile(
                    "ldmatrix.sync.aligned.m8n8.x4.shared.b16 {%0,%1,%2,%3}, [%4];"
                    : "=r"(a[mt][0]), "=r"(a[mt][1]), "=r"(a[mt][2]), "=r"(a[mt][3])
                    : "r"(pa));
            }
            uint32_t b[4][4];
            const uint32_t rowoff = (uint32_t)((16 * j + kl) << 7);
#pragma unroll
            for (int nt = 0; nt < 4; nt++) {
                uint32_t va = vst + uB[nt] + rowoff;
                asm volatile(
                    "ldmatrix.sync.aligned.m8n8.x4.trans.shared.b16 {%0,%1,%2,%3}, [%4];"
                    : "=r"(b[nt][0]), "=r"(b[nt][1]), "=r"(b[nt][2]), "=r"(b[nt][3])
                    : "r"(va));
            }
#pragma unroll
            for (int mt = 0; mt < 2; mt++)
#pragma unroll
                for (int nt = 0; nt < 4; nt++) {
                    MMA16816(acc[mt][2 * nt],     a[mt], b[nt][0], b[nt][1]);
                    MMA16816(acc[mt][2 * nt + 1], a[mt], b[nt][2], b[nt][3]);
                }
        }
    }

    // rowsum: thread pair (t, t^1) shares row er
    {
        float v = psum + __shfl_xor_sync(0xffffffffu, psum, 1);
        if (eh == 0) rowsum[er] = v;
    }
    __syncthreads();

    // epilogue: O = acc / (rowsum + exp(sink))
    const float sinkv = __expf(sinks[h]);
#pragma unroll
    for (int mt = 0; mt < 2; mt++)
#pragma unroll
        for (int a2 = 0; a2 < 2; a2++) {
            int r = 32 * qw + 16 * mt + 8 * a2 + g;
            float inv = 1.0f / (rowsum[r] + sinkv);
            float* orow = out + ((size_t)h * SQ_ + q0 + r) * DH_ + 64 * nh + m * 2;
#pragma unroll
            for (int nt = 0; nt < 8; nt++) {
                float2 o;
                o.x = acc[mt][nt][2 * a2 + 0] * inv;
                o.y = acc[mt][nt][2 * a2 + 1] * inv;
                *(float2*)(orow + nt * 8) = o;
            }
        }
}

// ---------------- Launch ----------------
extern "C" void kernel_launch(void* const* d_in, const int* in_sizes, int n_in,
                              void* d_out, int out_size) {
    const float* logits = nullptr;
    const float* value  = nullptr;
    const float* sinks  = nullptr;
    for (int i = 0; i < n_in; i++) {
        if (in_sizes[i] == H_) sinks = (const float*)d_in[i];
        else if (in_sizes[i] == H_ * SQ_ * SK_) logits = (const float*)d_in[i];
        else if (in_sizes[i] == H_ * SK_ * DH_) value = (const float*)d_in[i];
    }
    float* out = (float*)d_out;

    convert_v_kernel<<<(H_ * SK_ * DH_) / (256 * 8), 256>>>(value);

    cudaFuncSetAttribute(attn_sink_kernel,
                         cudaFuncAttributeMaxDynamicSharedMemorySize, SMEM_SZ);
    attn_sink_kernel<<<H_ * (SQ_ / QT), 256, SMEM_SZ>>>(logits, sinks, out);
}